// round 9
// baseline (speedup 1.0000x reference)
#include <cuda_runtime.h>
#include <cstdint>

// Problem constants
#define BB 128
#define TT 512
#define HALF 256
#define DD 512
#define G3D 1536
#define MROWS 32768   // BB*HALF
#define GRID_GRU 128

#define HT2 516       // GRU h-tile smem stride (f32)
#define WS2 516       // GRU W-slice smem stride
#define ASTR 36       // GEMM smem row stride (f32)
#define GEMM_BUF (128 * ASTR)                 // floats per buffer per operand
#define GEMM_SMEM (4 * GEMM_BUF * 4)          // bytes: 2 operands x 2 buffers

typedef unsigned long long ull;

// ---------------- scratch (static device allocations; no cudaMalloc) ----------------
__device__ float g_gx[(size_t)HALF * BB * G3D];   // [256,128,1536] input preacts (incl b_ih)
__device__ float g_P [(size_t)MROWS * DD];        // emotions, row = b*256+t
__device__ float g_t1[(size_t)MROWS * DD];
__device__ float g_t2[(size_t)MROWS * DD];
__device__ float g_h4[(size_t)MROWS * (DD/2)];
__device__ float g_lse[MROWS];
__device__ float g_s[DD/2];
__device__ float g_h[2 * BB * DD];                // ping-pong hidden state
__device__ unsigned g_flag[GRID_GRU];             // per-CTA generation flags

// ---------------- tf32 mma helpers ----------------
__device__ __forceinline__ float tf32r(float x) {
    uint32_t y; asm("cvt.rna.tf32.f32 %0, %1;" : "=r"(y) : "f"(x));
    return __uint_as_float(y);
}
__device__ __forceinline__ float4 tf32r4(float4 v) {
    return make_float4(tf32r(v.x), tf32r(v.y), tf32r(v.z), tf32r(v.w));
}
__device__ __forceinline__ void ldmat_x4(uint32_t addr, uint32_t &r0, uint32_t &r1,
                                         uint32_t &r2, uint32_t &r3) {
    asm volatile("ldmatrix.sync.aligned.m8n8.x4.shared.b16 {%0,%1,%2,%3}, [%4];"
                 : "=r"(r0), "=r"(r1), "=r"(r2), "=r"(r3) : "r"(addr));
}
__device__ __forceinline__ void mma_tf32(float* d, const uint32_t* a, uint32_t b0, uint32_t b1) {
    asm volatile("mma.sync.aligned.m16n8k8.row.col.f32.tf32.tf32.f32 "
                 "{%0,%1,%2,%3},{%4,%5,%6,%7},{%8,%9},{%0,%1,%2,%3};"
                 : "+f"(d[0]), "+f"(d[1]), "+f"(d[2]), "+f"(d[3])
                 : "r"(a[0]), "r"(a[1]), "r"(a[2]), "r"(a[3]), "r"(b0), "r"(b1));
}

// ---------------- tf32 tensor-core GEMM: C[M,N] = A[M,K] @ W[N,K]^T ----------------
// 128x128 tile, BK=32, double-buffered dynamic smem, 8 warps (4m x 2n), warp 32m x 64n.
// MODE_A: 0 = A row-major (lda=K); 1 = A is x0[B,T,D], logical row r -> b=r%128, t=r/128
// ACT: 0 = +bias ; 1 = tanh(+bias) ; 3 = +bias - lse[row]*s[col]
template<int MODE_A, int ACT>
__global__ __launch_bounds__(256)
void gemm_tc(const float* __restrict__ A, const float* __restrict__ W,
             const float* __restrict__ bias, float* __restrict__ C,
             int M, int N, int K,
             const float* __restrict__ lse, const float* __restrict__ svec)
{
    extern __shared__ float gsm[];
    float* A_s[2] = { gsm,                gsm + GEMM_BUF };
    float* W_s[2] = { gsm + 2 * GEMM_BUF, gsm + 3 * GEMM_BUF };

    const int tid = threadIdx.x;
    const int wid = tid >> 5, lane = tid & 31;
    const int m0 = blockIdx.y * 128;
    const int n0 = blockIdx.x * 128;
    const int mw = (wid & 3) * 32;
    const int nw = (wid >> 2) * 64;

    int lrow[4], lc4[4];
    const float* aptr[4];
    const float* wptr[4];
#pragma unroll
    for (int i = 0; i < 4; i++) {
        int f = tid + i * 256;
        lrow[i] = f >> 3; lc4[i] = f & 7;
        int gr = m0 + lrow[i];
        if (MODE_A == 1) {
            int b = gr & 127, t = gr >> 7;
            aptr[i] = A + ((size_t)b * TT + t) * DD;
        } else {
            aptr[i] = A + (size_t)gr * K;
        }
        wptr[i] = W + (size_t)(n0 + lrow[i]) * K;
    }

    float acc[2][8][4];
#pragma unroll
    for (int mi = 0; mi < 2; mi++)
#pragma unroll
        for (int nb = 0; nb < 8; nb++)
#pragma unroll
            for (int c = 0; c < 4; c++) acc[mi][nb][c] = 0.f;

    const int a_row = (lane & 15);
    const int a_k4  = (lane >> 4) * 4;
    const int w_row = (lane & 7);
    const int w_k4  = (lane >> 3) * 4;

    // preload chunk 0 and stage into buffer 0
    float4 an[4], wn[4];
#pragma unroll
    for (int i = 0; i < 4; i++) {
        an[i] = *(const float4*)(aptr[i] + lc4[i] * 4);
        wn[i] = *(const float4*)(wptr[i] + lc4[i] * 4);
    }
#pragma unroll
    for (int i = 0; i < 4; i++) {
        *(float4*)&A_s[0][lrow[i] * ASTR + lc4[i] * 4] = tf32r4(an[i]);
        *(float4*)&W_s[0][lrow[i] * ASTR + lc4[i] * 4] = tf32r4(wn[i]);
    }

    const int nc = K >> 5;
    for (int it = 0; it < nc; it++) {
        // prefetch next chunk into registers
        if (it + 1 < nc) {
            int kt = (it + 1) << 5;
#pragma unroll
            for (int i = 0; i < 4; i++) {
                an[i] = *(const float4*)(aptr[i] + kt + lc4[i] * 4);
                wn[i] = *(const float4*)(wptr[i] + kt + lc4[i] * 4);
            }
        }
        __syncthreads();
        // stage next chunk into the other buffer while computing on this one
        if (it + 1 < nc) {
            float* an_s = A_s[(it + 1) & 1];
            float* wn_s = W_s[(it + 1) & 1];
#pragma unroll
            for (int i = 0; i < 4; i++) {
                *(float4*)&an_s[lrow[i] * ASTR + lc4[i] * 4] = tf32r4(an[i]);
                *(float4*)&wn_s[lrow[i] * ASTR + lc4[i] * 4] = tf32r4(wn[i]);
            }
        }

        const uint32_t a_base = (uint32_t)__cvta_generic_to_shared(A_s[it & 1]);
        const uint32_t w_base = (uint32_t)__cvta_generic_to_shared(W_s[it & 1]);
#pragma unroll
        for (int kk = 0; kk < 32; kk += 16) {
            uint32_t a[2][2][4];
#pragma unroll
            for (int mi = 0; mi < 2; mi++)
#pragma unroll
                for (int ks = 0; ks < 2; ks++) {
                    uint32_t addr = a_base +
                        (((mw + mi * 16 + a_row) * ASTR + a_k4 + kk + ks * 8) << 2);
                    ldmat_x4(addr, a[mi][ks][0], a[mi][ks][1], a[mi][ks][2], a[mi][ks][3]);
                }
            // process nb in pairs: two ldsm in flight before their 8 mmas
#pragma unroll
            for (int nb = 0; nb < 8; nb += 2) {
                uint32_t b[2][4];
#pragma unroll
                for (int q = 0; q < 2; q++) {
                    uint32_t addr = w_base +
                        (((nw + (nb + q) * 8 + w_row) * ASTR + w_k4 + kk) << 2);
                    ldmat_x4(addr, b[q][0], b[q][1], b[q][2], b[q][3]);
                }
#pragma unroll
                for (int q = 0; q < 2; q++)
#pragma unroll
                    for (int mi = 0; mi < 2; mi++) {
                        mma_tf32(acc[mi][nb + q], a[mi][0], b[q][0], b[q][1]);
                        mma_tf32(acc[mi][nb + q], a[mi][1], b[q][2], b[q][3]);
                    }
            }
        }
    }

    // epilogue
#pragma unroll
    for (int mi = 0; mi < 2; mi++) {
        int r0 = m0 + mw + mi * 16 + (lane >> 2);
        float ls0 = 0.f, ls1 = 0.f;
        if (ACT == 3) { ls0 = lse[r0]; ls1 = lse[r0 + 8]; }
#pragma unroll
        for (int nb = 0; nb < 8; nb++) {
            int col = n0 + nw + nb * 8 + (lane & 3) * 2;
            float b0v = bias[col], b1v = bias[col + 1];
            float2 v0 = make_float2(acc[mi][nb][0] + b0v, acc[mi][nb][1] + b1v);
            float2 v1 = make_float2(acc[mi][nb][2] + b0v, acc[mi][nb][3] + b1v);
            if (ACT == 1) {
                v0.x = tanhf(v0.x); v0.y = tanhf(v0.y);
                v1.x = tanhf(v1.x); v1.y = tanhf(v1.y);
            }
            if (ACT == 3) {
                float s0 = svec[col], s1 = svec[col + 1];
                v0.x -= ls0 * s0; v0.y -= ls0 * s1;
                v1.x -= ls1 * s0; v1.y -= ls1 * s1;
            }
            *(float2*)&C[(size_t)r0 * N + col] = v0;
            *(float2*)&C[(size_t)(r0 + 8) * N + col] = v1;
        }
    }
}

// ---------------- persistent GRU: 256 steps, tensor-core per-step GEMM ----------------
// Grid 128 = 4 batch-groups (32 rows) x 32 unit-groups (16 units = 48 gate-rows).
// Warp split: wk = wid&3 (k-slice of 128), wn = wid>>2 (24 of 48 gate-rows).
// Distributed flag barrier: each CTA release-stores its step count; warp-0 lanes
// poll the 32 peer flags of their batch group in parallel.
__global__ __launch_bounds__(256, 1)
void gru_persistent_kernel(const float* __restrict__ gx,
                           const float* __restrict__ Whh,
                           const float* __restrict__ bhh,
                           float* __restrict__ hbuf,
                           float* __restrict__ P)
{
    extern __shared__ float sm[];
    float* htf = sm;                      // [32][516]  tf32-rounded h tile
    float* wsm = sm + 32 * HT2;           // [48][516]  tf32-rounded W slice, row j = u*3+g
    float* red = wsm + 48 * WS2;          // [4][1536]  k-slice partials; red[0..1535] = sums

    const int tid = threadIdx.x;
    const int wid = tid >> 5, lane = tid & 31;
    const int bg = blockIdx.x & 3, ug = blockIdx.x >> 2;
    const int bbase = bg * 32;
    const int ubase = ug * 16;
    const int wk = wid & 3, wn = wid >> 2;
    const int kbase = wk * 128;
    const int nbase = wn * 24;

    // load + tf32-round W slice once
    for (int f = tid; f < 48 * 128; f += 256) {
        int row = f >> 7, c4 = f & 127;
        int uu = row / 3, g = row - uu * 3;
        *(float4*)&wsm[row * WS2 + c4 * 4] =
            tf32r4(*(const float4*)&Whh[(size_t)(g * 512 + ubase + uu) * 512 + c4 * 4]);
    }

    // per-thread update-phase constants (2 outputs per thread)
    int ub[2], uu2[2];
    float bh0[2], bh1[2], bh2[2];
#pragma unroll
    for (int s = 0; s < 2; s++) {
        int idx = tid + 256 * s;
        ub[s] = idx >> 4;
        uu2[s] = idx & 15;
        int d = ubase + uu2[s];
        bh0[s] = bhh[d]; bh1[s] = bhh[512 + d]; bh2[s] = bhh[1024 + d];
    }

    const int a_row = (lane & 15);
    const int a_k4  = (lane >> 4) * 4;
    const int w_row = (lane & 7);
    const int w_k4  = (lane >> 3) * 4;
    const uint32_t h_base = (uint32_t)__cvta_generic_to_shared(htf);
    const uint32_t w_base = (uint32_t)__cvta_generic_to_shared(wsm);

    for (int t = 0; t < HALF; t++) {
        const float* hsrc = hbuf + (t & 1) * (BB * DD);

        // ---- early prefetch: gx operands + own previous-h values ----
        float xr[2], xz[2], xn[2], hp[2];
        {
            const float* gxt = gx + (size_t)t * BB * G3D;
#pragma unroll
            for (int s = 0; s < 2; s++) {
                const float* gxp = gxt + (size_t)(bbase + ub[s]) * G3D + ubase + uu2[s];
                xr[s] = __ldg(gxp);
                xz[s] = __ldg(gxp + 512);
                xn[s] = __ldg(gxp + 1024);
                hp[s] = (t == 0) ? 0.f
                        : __ldg(&hsrc[(size_t)(bbase + ub[s]) * DD + ubase + uu2[s]]);
            }
        }

        // ---- load h tile, tf32-round into smem ----
        if (t == 0) {
            float4 z = make_float4(0.f, 0.f, 0.f, 0.f);
            for (int f = tid; f < 32 * 128; f += 256) {
                int row = f >> 7, c4 = f & 127;
                *(float4*)&htf[row * HT2 + c4 * 4] = z;
            }
        } else {
            for (int f = tid; f < 32 * 128; f += 256) {
                int row = f >> 7, c4 = f & 127;
                *(float4*)&htf[row * HT2 + c4 * 4] =
                    tf32r4(*(const float4*)&hsrc[(size_t)(bbase + row) * DD + c4 * 4]);
            }
        }
        __syncthreads();

        // ---- warp tile: 32m x 24n x 128k via mma ----
        float acc[2][3][4];
#pragma unroll
        for (int mi = 0; mi < 2; mi++)
#pragma unroll
            for (int nb = 0; nb < 3; nb++)
#pragma unroll
                for (int c = 0; c < 4; c++) acc[mi][nb][c] = 0.f;

#pragma unroll
        for (int kk = 0; kk < 128; kk += 16) {
            uint32_t a[2][2][4];
#pragma unroll
            for (int mi = 0; mi < 2; mi++)
#pragma unroll
                for (int ks = 0; ks < 2; ks++) {
                    uint32_t addr = h_base +
                        (((mi * 16 + a_row) * HT2 + kbase + kk + ks * 8 + a_k4) << 2);
                    ldmat_x4(addr, a[mi][ks][0], a[mi][ks][1], a[mi][ks][2], a[mi][ks][3]);
                }
#pragma unroll
            for (int nb = 0; nb < 3; nb++) {
                uint32_t b0, b1, b2, b3;
                uint32_t addr = w_base +
                    (((nbase + nb * 8 + w_row) * WS2 + kbase + kk + w_k4) << 2);
                ldmat_x4(addr, b0, b1, b2, b3);
#pragma unroll
                for (int mi = 0; mi < 2; mi++) {
                    mma_tf32(acc[mi][nb], a[mi][0], b0, b1);
                    mma_tf32(acc[mi][nb], a[mi][1], b2, b3);
                }
            }
        }

        // ---- write k-slice partials to red[wk][bl*48 + nbase + n] ----
#pragma unroll
        for (int mi = 0; mi < 2; mi++) {
            int bl = mi * 16 + (lane >> 2);
#pragma unroll
            for (int nb = 0; nb < 3; nb++) {
                int n = nbase + nb * 8 + (lane & 3) * 2;
                *(float2*)&red[wk * 1536 + bl * 48 + n] =
                    make_float2(acc[mi][nb][0], acc[mi][nb][1]);
                *(float2*)&red[wk * 1536 + (bl + 8) * 48 + n] =
                    make_float2(acc[mi][nb][2], acc[mi][nb][3]);
            }
        }
        __syncthreads();

        // ---- reduce 4 k-slice partials ----
#pragma unroll
        for (int s = 0; s < 6; s++) {
            int o = tid + 256 * s;
            float v = red[o] + red[1536 + o] + red[2 * 1536 + o] + red[3 * 1536 + o];
            red[o] = v;
        }
        __syncthreads();

        // ---- gate math + update ----
        float* hdst = hbuf + ((t + 1) & 1) * (BB * DD);
#pragma unroll
        for (int s = 0; s < 2; s++) {
            int b = ub[s], u = uu2[s];
            int d = ubase + u;
            int gb = bbase + b;
            float hr = red[b * 48 + u * 3 + 0] + bh0[s];
            float hz = red[b * 48 + u * 3 + 1] + bh1[s];
            float hn = red[b * 48 + u * 3 + 2] + bh2[s];
            float rg = 1.f / (1.f + expf(-(xr[s] + hr)));
            float zg = 1.f / (1.f + expf(-(xz[s] + hz)));
            float ng = tanhf(xn[s] + rg * hn);
            float hnew = (1.f - zg) * ng + zg * hp[s];
            hdst[(size_t)gb * DD + d] = hnew;
            P[((size_t)gb * HALF + t) * DD + d] = hnew;
        }

        // ---- distributed flag barrier (32 CTAs of this batch group) ----
        if (t < HALF - 1) {
            __threadfence();
            __syncthreads();
            if (tid == 0) {
                asm volatile("st.release.gpu.u32 [%0], %1;"
                             :: "l"(&g_flag[blockIdx.x]), "r"((unsigned)(t + 1)) : "memory");
            }
            if (tid < 32) {
                const unsigned* fp = &g_flag[bg + 4 * tid];
                unsigned v;
                do {
                    asm volatile("ld.acquire.gpu.u32 %0, [%1];"
                                 : "=r"(v) : "l"(fp) : "memory");
                    if (v < (unsigned)(t + 1)) __nanosleep(16);
                } while (v < (unsigned)(t + 1));
            }
            __syncthreads();
        }
    }
}

// ---------------- small kernels ----------------
__global__ void bar_init_kernel() {
    if (threadIdx.x < GRID_GRU) g_flag[threadIdx.x] = 0u;
}

__global__ __launch_bounds__(256)
void lse_kernel(const float* __restrict__ X, float* __restrict__ lse) {
    int warp = threadIdx.x >> 5, lane = threadIdx.x & 31;
    int row = blockIdx.x * 8 + warp;
    const float* x = X + (size_t)row * 512;
    float v[16];
#pragma unroll
    for (int i = 0; i < 4; i++) {
        float4 f = *(const float4*)&x[lane * 4 + i * 128];
        v[i * 4 + 0] = f.x; v[i * 4 + 1] = f.y; v[i * 4 + 2] = f.z; v[i * 4 + 3] = f.w;
    }
    float m = v[0];
#pragma unroll
    for (int i = 1; i < 16; i++) m = fmaxf(m, v[i]);
#pragma unroll
    for (int o = 16; o; o >>= 1) m = fmaxf(m, __shfl_xor_sync(0xffffffffu, m, o));
    float s = 0.f;
#pragma unroll
    for (int i = 0; i < 16; i++) s += expf(v[i] - m);
#pragma unroll
    for (int o = 16; o; o >>= 1) s += __shfl_xor_sync(0xffffffffu, s, o);
    if (lane == 0) lse[row] = m + logf(s);
}

__global__ void ssum_kernel(const float* __restrict__ Wh, float* __restrict__ s) {
    int j = threadIdx.x;   // 256
    float acc = 0.f;
    for (int k = 0; k < 512; k++) acc += Wh[(size_t)j * 512 + k];
    s[j] = acc;
}

__global__ __launch_bounds__(256)
void head_kernel(const float* __restrict__ H, const float* __restrict__ Wout,
                 const float* __restrict__ bout, float* __restrict__ out) {
    __shared__ float Ws[7][256];
    int tid = threadIdx.x;
    for (int f = tid; f < 7 * 256; f += 256) Ws[f >> 8][f & 255] = Wout[f];
    __syncthreads();
    int warp = tid >> 5, lane = tid & 31;
    int row = blockIdx.x * 8 + warp;
    const float* h = H + (size_t)row * 256;
    float hv[8];
    *(float4*)&hv[0] = *(const float4*)&h[lane * 8];
    *(float4*)&hv[4] = *(const float4*)&h[lane * 8 + 4];
#pragma unroll
    for (int c = 0; c < 7; c++) {
        float a = 0.f;
#pragma unroll
        for (int j = 0; j < 8; j++) a += hv[j] * Ws[c][lane * 8 + j];
#pragma unroll
        for (int o = 16; o; o >>= 1) a += __shfl_xor_sync(0xffffffffu, a, o);
        if (lane == c) out[(size_t)row * 7 + c] = a + bout[c];
    }
}

// ---------------- launch ----------------
extern "C" void kernel_launch(void* const* d_in, const int* in_sizes, int n_in,
                              void* d_out, int out_size)
{
    const float* x0   = (const float*)d_in[0];
    const float* W_ih = (const float*)d_in[3];
    const float* W_hh = (const float*)d_in[4];
    const float* b_ih = (const float*)d_in[5];
    const float* b_hh = (const float*)d_in[6];
    const float* W1   = (const float*)d_in[7];
    const float* b1   = (const float*)d_in[8];
    const float* W2   = (const float*)d_in[9];
    const float* b2   = (const float*)d_in[10];
    const float* W3   = (const float*)d_in[11];
    const float* b3   = (const float*)d_in[12];
    const float* Wh   = (const float*)d_in[13];
    const float* bh   = (const float*)d_in[14];
    const float* Wo   = (const float*)d_in[15];
    const float* bo   = (const float*)d_in[16];
    float* out = (float*)d_out;

    float *gx, *P, *t1, *t2, *h4, *lse, *s, *hbuf;
    cudaGetSymbolAddress((void**)&gx,  g_gx);
    cudaGetSymbolAddress((void**)&P,   g_P);
    cudaGetSymbolAddress((void**)&t1,  g_t1);
    cudaGetSymbolAddress((void**)&t2,  g_t2);
    cudaGetSymbolAddress((void**)&h4,  g_h4);
    cudaGetSymbolAddress((void**)&lse, g_lse);
    cudaGetSymbolAddress((void**)&s,   g_s);
    cudaGetSymbolAddress((void**)&hbuf, g_h);

    const int GRU_SMEM = (32 * HT2 + 48 * WS2 + 4 * 1536) * 4;  // 189,696 B
    cudaFuncSetAttribute(gru_persistent_kernel,
                         cudaFuncAttributeMaxDynamicSharedMemorySize, GRU_SMEM);
    cudaFuncSetAttribute(gemm_tc<1, 0>,
                         cudaFuncAttributeMaxDynamicSharedMemorySize, GEMM_SMEM);
    cudaFuncSetAttribute(gemm_tc<0, 0>,
                         cudaFuncAttributeMaxDynamicSharedMemorySize, GEMM_SMEM);
    cudaFuncSetAttribute(gemm_tc<0, 1>,
                         cudaFuncAttributeMaxDynamicSharedMemorySize, GEMM_SMEM);
    cudaFuncSetAttribute(gemm_tc<0, 3>,
                         cudaFuncAttributeMaxDynamicSharedMemorySize, GEMM_SMEM);

    // reset barrier flags (deterministic per call)
    bar_init_kernel<<<1, 128>>>();

    // gx = x0[:, :256, :] @ W_ih^T + b_ih   (rows ordered r = t*128 + b)
    gemm_tc<1, 0><<<dim3(12, 256), 256, GEMM_SMEM>>>(x0, W_ih, b_ih, gx, MROWS, G3D, DD, nullptr, nullptr);

    // GRU recurrence: one persistent launch, 256 steps internally
    gru_persistent_kernel<<<GRID_GRU, 256, GRU_SMEM>>>(gx, W_hh, b_hh, hbuf, P);

    // FFN
    gemm_tc<0, 1><<<dim3(4, 256), 256, GEMM_SMEM>>>(P,  W1, b1, t1, MROWS, DD, DD, nullptr, nullptr);
    gemm_tc<0, 1><<<dim3(4, 256), 256, GEMM_SMEM>>>(t1, W2, b2, t2, MROWS, DD, DD, nullptr, nullptr);
    gemm_tc<0, 0><<<dim3(4, 256), 256, GEMM_SMEM>>>(t2, W3, b3, t1, MROWS, DD, DD, nullptr, nullptr);

    // folded log_softmax + half head
    lse_kernel<<<4096, 256>>>(t1, lse);
    ssum_kernel<<<1, 256>>>(Wh, s);
    gemm_tc<0, 3><<<dim3(2, 256), 256, GEMM_SMEM>>>(t1, Wh, bh, h4, MROWS, DD / 2, DD, lse, s);

    // final head -> out [32768, 7]
    head_kernel<<<4096, 256>>>(h4, Wo, bo, out);
}